// round 6
// baseline (speedup 1.0000x reference)
#include <cuda_runtime.h>

// Problem constants (fixed by the reference: N=16384, D=2, H=128)
constexpr int N_ROWS = 16384;
constexpr int H      = 128;
constexpr int NHi    = N_ROWS * H;          // floats per [N,H] tensor

// K1: streaming pass (barrier-free, runs at memory speed)
constexpr int THREADS  = 256;
constexpr int WPB      = 8;                          // warps per block
constexpr int BLOCKS1  = 1024;
constexpr int TW1      = BLOCKS1 * WPB;              // 8192 warps
constexpr int RPW1     = N_ROWS / TW1;               // 2 rows/warp

// K2: nce pass — ONE ROW PER WARP, no loop, max latency hiding
constexpr int BLOCKS2  = N_ROWS / WPB;               // 2048 blocks

// Persistent scratch (allocation-free __device__ globals). Zero at module
// load; K2's ticket-elected last block re-zeros for the next graph replay.
__device__ float    g_h[N_ROWS];     // per-row: -N*||e||^2 + 10*diag
__device__ float    g_ysum[H];       // sum_y bi_dec[y][c]
__device__ float    g_scalars[3];    // [0]=Synorm  [1]=sum diag  [2]=nce
__device__ unsigned g_ticket;        // last-block election in K2

__device__ __forceinline__ float warp_sum(float v) {
    #pragma unroll
    for (int o = 16; o > 0; o >>= 1) v += __shfl_down_sync(0xffffffffu, v, o);
    return v;
}

// ---------------------------------------------------------------------------
// K1: stream enc+dec once (33.5 MB in, 25.2 MB out). Emits bi_enc (x2),
// bi_dec, per-row h, and accumulates Ysum / Synorm / sum-diag via block-
// reduced atomics. No barrier: blocks retire independently.
// ---------------------------------------------------------------------------
__global__ __launch_bounds__(THREADS) void stream_kernel(
    const float* __restrict__ enc, const float* __restrict__ dec,
    float* __restrict__ out)
{
    const int tid   = threadIdx.x;
    const int lane  = tid & 31;
    const int w     = tid >> 5;
    const int gwarp = blockIdx.x * WPB + w;

    float ys0 = 0.f, ys1 = 0.f, ys2 = 0.f, ys3 = 0.f;
    float ynorm = 0.f, dgsum = 0.f;

    #pragma unroll
    for (int i = 0; i < RPW1; i++) {
        const int r = gwarp + i * TW1;
        // row r = 256 floats = 64 float4; direction halves at +0 / +32
        const float4 a = __ldg((const float4*)enc + r * 64 + lane);
        const float4 b = __ldg((const float4*)enc + r * 64 + 32 + lane);
        const float4 c = __ldg((const float4*)dec + r * 64 + lane);
        const float4 d = __ldg((const float4*)dec + r * 64 + 32 + lane);

        float4 e; e.x = a.x + b.x; e.y = a.y + b.y; e.z = a.z + b.z; e.w = a.w + b.w;
        float4 f; f.x = c.x + d.x; f.y = c.y + d.y; f.z = c.z + d.z; f.w = c.w + d.w;

        ((float4*)out)[          r * 32 + lane] = e;   // bi_enc
        ((float4*)out)[NHi / 4 + r * 32 + lane] = e;   // bi_enc (again)
        ((float4*)out)[NHi / 2 + r * 32 + lane] = f;   // bi_dec

        ys0 += f.x; ys1 += f.y; ys2 += f.z; ys3 += f.w;
        ynorm += f.x * f.x + f.y * f.y + f.z * f.z + f.w * f.w;

        const float en  = e.x * e.x + e.y * e.y + e.z * e.z + e.w * e.w;
        const float gx = e.x - f.x, gy = e.y - f.y, gz = e.z - f.z, gw = e.w - f.w;
        const float dgl = gx * gx + gy * gy + gz * gz + gw * gw;

        dgsum += dgl;
        float h = warp_sum(fmaf(-(float)N_ROWS, en, 10.0f * dgl));
        if (lane == 0) g_h[r] = h;
    }
    ynorm = warp_sum(ynorm);
    dgsum = warp_sum(dgsum);

    __shared__ float s_ys[WPB][H];
    __shared__ float s_sc[WPB][2];
    s_ys[w][4 * lane + 0] = ys0;
    s_ys[w][4 * lane + 1] = ys1;
    s_ys[w][4 * lane + 2] = ys2;
    s_ys[w][4 * lane + 3] = ys3;
    if (lane == 0) { s_sc[w][0] = ynorm; s_sc[w][1] = dgsum; }
    __syncthreads();

    if (tid < H) {
        float s = 0.f;
        #pragma unroll
        for (int ww = 0; ww < WPB; ww++) s += s_ys[ww][tid];
        atomicAdd(&g_ysum[tid], s);
    } else if (tid == H) {
        float yn = 0.f, ds = 0.f;
        #pragma unroll
        for (int ww = 0; ww < WPB; ww++) { yn += s_sc[ww][0]; ds += s_sc[ww][1]; }
        atomicAdd(&g_scalars[0], yn);
        atomicAdd(&g_scalars[1], ds);
    }
}

// ---------------------------------------------------------------------------
// K2: nce. One warp per row — single LDG.128 (L2-resident bi_enc), one dot,
// one shuffle chain, no loop. 16384 warps hide all latency.
// ---------------------------------------------------------------------------
__global__ __launch_bounds__(THREADS) void nce_kernel(float* __restrict__ out)
{
    const int tid  = threadIdx.x;
    const int lane = tid & 31;
    const int w    = tid >> 5;
    const int r    = blockIdx.x * WPB + w;           // one row per warp

    const float4 ys = ((const float4*)g_ysum)[lane];
    const float4 e  = __ldg((const float4*)out + r * 32 + lane);   // bi_enc (L2)

    float dp = e.x * ys.x + e.y * ys.y + e.z * ys.z + e.w * ys.w;
    dp = warp_sum(dp);

    __shared__ float s_nce[WPB];
    if (lane == 0) {
        const float row_loss = 5.0f - g_scalars[0] + fmaf(2.0f, dp, g_h[r]);
        s_nce[w] = fmaxf(row_loss, 0.0f);
    }
    __syncthreads();

    if (tid == 0) {
        float tn = 0.f;
        #pragma unroll
        for (int ww = 0; ww < WPB; ww++) tn += s_nce[ww];
        atomicAdd(&g_scalars[2], tn);
        __threadfence();
        // Last-arriving block writes scalar outputs and re-zeros state.
        if (atomicAdd(&g_ticket, 1u) == BLOCKS2 - 1) {
            const float nce  = atomicAdd(&g_scalars[2], 0.0f);
            const float diag = g_scalars[1];
            out[3 * NHi]     = nce;                        // nce_loss
            out[3 * NHi + 1] = -diag / (float)N_ROWS;      // diagonal_loss
            #pragma unroll
            for (int i = 0; i < H; i++) g_ysum[i] = 0.0f;
            g_scalars[0] = 0.0f; g_scalars[1] = 0.0f; g_scalars[2] = 0.0f;
            atomicExch(&g_ticket, 0u);
        }
    }
}

extern "C" void kernel_launch(void* const* d_in, const int* in_sizes, int n_in,
                              void* d_out, int out_size) {
    const float* enc = (const float*)d_in[0];
    const float* dec = (const float*)d_in[1];
    float* out = (float*)d_out;

    stream_kernel<<<BLOCKS1, THREADS>>>(enc, dec, out);
    nce_kernel<<<BLOCKS2, THREADS>>>(out);
}

// round 7
// speedup vs baseline: 1.1235x; 1.1235x over previous
#include <cuda_runtime.h>

// Problem constants (fixed by the reference: N=16384, D=2, H=128)
constexpr int N_ROWS = 16384;
constexpr int H      = 128;
constexpr int NHi    = N_ROWS * H;          // floats per [N,H] tensor

constexpr int THREADS  = 256;
constexpr int WPB      = 8;                          // warps per block

// K1: streaming pass
constexpr int BLOCKS1  = 1024;
constexpr int TW1      = BLOCKS1 * WPB;              // 8192 warps
constexpr int RPW1     = N_ROWS / TW1;               // 2 rows/warp

// K2: nce pass — 4 contiguous rows per warp, everything prefetched
constexpr int BLOCKS2  = 512;
constexpr int RPW2     = 4;                          // rows per warp (fixed)

// Persistent scratch (allocation-free __device__ globals). Zero at module
// load; K2's ticket-elected last block re-zeros for the next graph replay.
__device__ float    g_h[N_ROWS];     // per-row: -N*||e||^2 + 10*diag
__device__ float    g_ysum[H];       // sum_y bi_dec[y][c]
__device__ float    g_scalars[3];    // [0]=Synorm  [1]=sum diag  [2]=nce
__device__ unsigned g_ticket;        // last-block election in K2

__device__ __forceinline__ float warp_sum(float v) {
    #pragma unroll
    for (int o = 16; o > 0; o >>= 1) v += __shfl_down_sync(0xffffffffu, v, o);
    return v;
}
__device__ __forceinline__ float warp_sum_xor(float v) {   // result in ALL lanes
    #pragma unroll
    for (int o = 16; o > 0; o >>= 1) v += __shfl_xor_sync(0xffffffffu, v, o);
    return v;
}

// ---------------------------------------------------------------------------
// K1: stream enc+dec once (33.5 MB in, 25.2 MB out). h warp-reductions are
// deferred to AFTER the load/store loop so no shfl chain blocks the stream.
// ---------------------------------------------------------------------------
__global__ __launch_bounds__(THREADS) void stream_kernel(
    const float* __restrict__ enc, const float* __restrict__ dec,
    float* __restrict__ out)
{
    const int tid   = threadIdx.x;
    const int lane  = tid & 31;
    const int w     = tid >> 5;
    const int gwarp = blockIdx.x * WPB + w;

    float ys0 = 0.f, ys1 = 0.f, ys2 = 0.f, ys3 = 0.f;
    float ynorm = 0.f, dgsum = 0.f;
    float hp[RPW1];                       // per-lane h partial per row

    #pragma unroll
    for (int i = 0; i < RPW1; i++) {
        const int r = gwarp + i * TW1;
        // row r = 256 floats = 64 float4; direction halves at +0 / +32
        const float4 a = __ldg((const float4*)enc + r * 64 + lane);
        const float4 b = __ldg((const float4*)enc + r * 64 + 32 + lane);
        const float4 c = __ldg((const float4*)dec + r * 64 + lane);
        const float4 d = __ldg((const float4*)dec + r * 64 + 32 + lane);

        float4 e; e.x = a.x + b.x; e.y = a.y + b.y; e.z = a.z + b.z; e.w = a.w + b.w;
        float4 f; f.x = c.x + d.x; f.y = c.y + d.y; f.z = c.z + d.z; f.w = c.w + d.w;

        ((float4*)out)[r * 32 + lane] = e;                   // bi_enc (K2 re-reads; keep in L2)
        __stcs((float4*)out + NHi / 4 + r * 32 + lane, e);   // bi_enc copy (evict-first)
        __stcs((float4*)out + NHi / 2 + r * 32 + lane, f);   // bi_dec     (evict-first)

        ys0 += f.x; ys1 += f.y; ys2 += f.z; ys3 += f.w;
        ynorm += f.x * f.x + f.y * f.y + f.z * f.z + f.w * f.w;

        const float en  = e.x * e.x + e.y * e.y + e.z * e.z + e.w * e.w;
        const float gx = e.x - f.x, gy = e.y - f.y, gz = e.z - f.z, gw = e.w - f.w;
        const float dgl = gx * gx + gy * gy + gz * gz + gw * gw;

        dgsum += dgl;
        hp[i] = fmaf(-(float)N_ROWS, en, 10.0f * dgl);
    }

    // Deferred reductions: 4 independent shfl chains, interleaved by ptxas.
    float h0 = hp[0], h1 = hp[1];
    #pragma unroll
    for (int o = 16; o > 0; o >>= 1) {
        h0    += __shfl_down_sync(0xffffffffu, h0, o);
        h1    += __shfl_down_sync(0xffffffffu, h1, o);
        ynorm += __shfl_down_sync(0xffffffffu, ynorm, o);
        dgsum += __shfl_down_sync(0xffffffffu, dgsum, o);
    }
    if (lane == 0) {
        g_h[gwarp]       = h0;
        g_h[gwarp + TW1] = h1;
    }

    __shared__ float s_ys[WPB][H];
    __shared__ float s_sc[WPB][2];
    s_ys[w][4 * lane + 0] = ys0;
    s_ys[w][4 * lane + 1] = ys1;
    s_ys[w][4 * lane + 2] = ys2;
    s_ys[w][4 * lane + 3] = ys3;
    if (lane == 0) { s_sc[w][0] = ynorm; s_sc[w][1] = dgsum; }
    __syncthreads();

    if (tid < H) {
        float s = 0.f;
        #pragma unroll
        for (int ww = 0; ww < WPB; ww++) s += s_ys[ww][tid];
        atomicAdd(&g_ysum[tid], s);
    } else if (tid == H) {
        float yn = 0.f, ds = 0.f;
        #pragma unroll
        for (int ww = 0; ww < WPB; ww++) { yn += s_sc[ww][0]; ds += s_sc[ww][1]; }
        atomicAdd(&g_scalars[0], yn);
        atomicAdd(&g_scalars[1], ds);
    }
}

// ---------------------------------------------------------------------------
// K2: nce. 4 contiguous rows per warp. ALL memory issued up front; 4
// independent butterfly reductions overlap; no lane-0 serial loads anywhere.
// ---------------------------------------------------------------------------
__global__ __launch_bounds__(THREADS) void nce_kernel(float* __restrict__ out)
{
    const int tid   = threadIdx.x;
    const int lane  = tid & 31;
    const int w     = tid >> 5;
    const int rbase = (blockIdx.x * WPB + w) * RPW2;     // 4 contiguous rows

    // ---- issue every load before any dependent math ----
    const float4 e0 = __ldg((const float4*)out + (rbase + 0) * 32 + lane);
    const float4 e1 = __ldg((const float4*)out + (rbase + 1) * 32 + lane);
    const float4 e2 = __ldg((const float4*)out + (rbase + 2) * 32 + lane);
    const float4 e3 = __ldg((const float4*)out + (rbase + 3) * 32 + lane);
    const float  hv = __ldg(&g_h[rbase + (lane & 3)]);   // lane l holds h[row l&3]
    const float4 ys = ((const float4*)g_ysum)[lane];
    const float  syn = g_scalars[0];

    float dp0 = e0.x * ys.x + e0.y * ys.y + e0.z * ys.z + e0.w * ys.w;
    float dp1 = e1.x * ys.x + e1.y * ys.y + e1.z * ys.z + e1.w * ys.w;
    float dp2 = e2.x * ys.x + e2.y * ys.y + e2.z * ys.z + e2.w * ys.w;
    float dp3 = e3.x * ys.x + e3.y * ys.y + e3.z * ys.z + e3.w * ys.w;

    // 4 independent butterflies (ILP-4 through the shfl pipe)
    #pragma unroll
    for (int o = 16; o > 0; o >>= 1) {
        dp0 += __shfl_xor_sync(0xffffffffu, dp0, o);
        dp1 += __shfl_xor_sync(0xffffffffu, dp1, o);
        dp2 += __shfl_xor_sync(0xffffffffu, dp2, o);
        dp3 += __shfl_xor_sync(0xffffffffu, dp3, o);
    }

    // lanes 0..3 finalize their row in parallel (h already lane-local)
    float dsel = dp0;
    if (lane == 1) dsel = dp1;
    else if (lane == 2) dsel = dp2;
    else if (lane == 3) dsel = dp3;

    float acc = 0.f;
    if (lane < 4)
        acc = fmaxf(5.0f - syn + fmaf(2.0f, dsel, hv), 0.0f);
    acc += __shfl_xor_sync(0xffffffffu, acc, 1);
    acc += __shfl_xor_sync(0xffffffffu, acc, 2);     // lane 0: warp total

    __shared__ float s_nce[WPB];
    if (lane == 0) s_nce[w] = acc;
    __syncthreads();

    if (tid == 0) {
        float tn = 0.f;
        #pragma unroll
        for (int ww = 0; ww < WPB; ww++) tn += s_nce[ww];
        atomicAdd(&g_scalars[2], tn);
        __threadfence();
        // Last-arriving block writes scalar outputs and re-zeros state.
        if (atomicAdd(&g_ticket, 1u) == BLOCKS2 - 1) {
            const float nce  = atomicAdd(&g_scalars[2], 0.0f);
            const float diag = g_scalars[1];
            out[3 * NHi]     = nce;                        // nce_loss
            out[3 * NHi + 1] = -diag / (float)N_ROWS;      // diagonal_loss
            #pragma unroll
            for (int i = 0; i < H; i++) g_ysum[i] = 0.0f;
            g_scalars[0] = 0.0f; g_scalars[1] = 0.0f; g_scalars[2] = 0.0f;
            atomicExch(&g_ticket, 0u);
        }
    }
}

extern "C" void kernel_launch(void* const* d_in, const int* in_sizes, int n_in,
                              void* d_out, int out_size) {
    const float* enc = (const float*)d_in[0];
    const float* dec = (const float*)d_in[1];
    float* out = (float*)d_out;

    stream_kernel<<<BLOCKS1, THREADS>>>(enc, dec, out);
    nce_kernel<<<BLOCKS2, THREADS>>>(out);
}